// round 8
// baseline (speedup 1.0000x reference)
#include <cuda_runtime.h>
#include <cstdint>

// Problem constants (fixed by the reference setup).
#define BATCH 16
#define SEQ   4096
#define DIM   256            // floats per frame
#define QUADS (DIM / 4)      // 64 float4 per frame

#define THREADS      512
#define WARPS        16
#define S_PER_BLOCK  32                          // two s per warp
#define BLOCKS_PER_BATCH (SEQ / S_PER_BLOCK)     // 128
#define NCOPY_BLOCKS (BATCH * BLOCKS_PER_BATCH)  // 2048
#define ZF_FRAMES    256                         // frames per zero-fill block

// ---------------------------------------------------------------------------
// Single kernel, no scratch, no inter-block dependency. Two roles:
//  - copy blocks [0, 2048): 16 warps, 32 s values per block (2 per warp).
//    The block recomputes the exclusive prefix sum(dims[b, 0:s_base)) locally
//    (dims is 256KB total, L2-resident); a 32-lane warp scan gives intra-block
//    offsets; each warp streams its two prefetched 1KB x rows out d times.
//  - zero-fill blocks: block-reduce the duration row -> total_b, then pad
//    frames >= total_b with zeros (stripes fully covered exit fast).
// ---------------------------------------------------------------------------
__global__ __launch_bounds__(THREADS) void expand_kernel(
    const float* __restrict__ x,     // [B, S, D]
    const int*   __restrict__ dims,  // [B, S]
    float* __restrict__ out,         // [B, T, D]
    int T, int zb_per_batch)
{
    const int tid  = threadIdx.x;
    const int warp = tid >> 5;
    const int lane = tid & 31;

    __shared__ int ws[WARPS];

    if (blockIdx.x < NCOPY_BLOCKS) {
        // ================= copy role =================
        const int cb     = blockIdx.x;
        const int b      = cb >> 7;             // 128 blocks per batch
        const int c      = cb & 127;
        const int s_base = c << 5;              // first s of this block (mult of 32)

        const int* __restrict__ drow = dims + (size_t)b * SEQ;

        // --- issue prefix-range loads FIRST (latency overlaps x prefetch) ---
        const int  n4 = s_base >> 2;            // int4 count, <= 1016
        const int4* dp = reinterpret_cast<const int4*>(drow);
        int4 q0 = make_int4(0,0,0,0), q1 = make_int4(0,0,0,0);
        if (tid < n4)           q0 = __ldg(dp + tid);
        if (tid + THREADS < n4) q1 = __ldg(dp + tid + THREADS);

        // This block's 32 durations (lanes 0..31, coalesced).
        const int dval = __ldg(drow + s_base + lane);

        // --- prefetch this warp's two source rows (4 independent LDG.128) ---
        const int s_a = s_base + warp;
        const int s_b = s_base + warp + 16;
        const float4* __restrict__ srcA =
            reinterpret_cast<const float4*>(x) + ((size_t)b * SEQ + s_a) * QUADS;
        const float4* __restrict__ srcB =
            reinterpret_cast<const float4*>(x) + ((size_t)b * SEQ + s_b) * QUADS;
        const float4 a0 = __ldg(srcA + lane);
        const float4 a1 = __ldg(srcA + lane + 32);
        const float4 b0 = __ldg(srcB + lane);
        const float4 b1 = __ldg(srcB + lane + 32);

        // --- block reduce of the prefix range ---
        int acc = q0.x + q0.y + q0.z + q0.w + q1.x + q1.y + q1.z + q1.w;
        acc = __reduce_add_sync(0xFFFFFFFFu, acc);
        if (lane == 0) ws[warp] = acc;
        __syncthreads();
        int prefix = 0;
        #pragma unroll
        for (int i = 0; i < WARPS; i++) prefix += ws[i];

        // --- 32-lane inclusive scan of this block's durations ---
        int sc = dval;
        #pragma unroll
        for (int off = 1; off < 32; off <<= 1) {
            const int n = __shfl_up_sync(0xFFFFFFFFu, sc, off);
            if (lane >= off) sc += n;
        }
        // Exclusive starts / durations for this warp's two rows.
        const int dA = __shfl_sync(0xFFFFFFFFu, dval, warp);
        const int iA = __shfl_sync(0xFFFFFFFFu, sc,   warp);
        const int dB = __shfl_sync(0xFFFFFFFFu, dval, warp + 16);
        const int iB = __shfl_sync(0xFFFFFFFFu, sc,   warp + 16);
        const int startA = prefix + iA - dA;
        const int startB = prefix + iB - dB;

        float4* __restrict__ ob = reinterpret_cast<float4*>(out) + (size_t)b * T * QUADS;

        float4* o = ob + (size_t)startA * QUADS;
        for (int k = 0; k < dA; k++) {
            __stcs(o + lane,      a0);
            __stcs(o + lane + 32, a1);
            o += QUADS;
        }
        o = ob + (size_t)startB * QUADS;
        for (int k = 0; k < dB; k++) {
            __stcs(o + lane,      b0);
            __stcs(o + lane + 32, b1);
            o += QUADS;
        }
        return;
    }

    // ================= zero-fill role =================
    {
        const int zb = blockIdx.x - NCOPY_BLOCKS;
        const int b  = zb / zb_per_batch;
        const int j  = zb - b * zb_per_batch;

        // Block-reduce the full duration row -> total_b (1024 int4).
        const int4* dp = reinterpret_cast<const int4*>(dims + (size_t)b * SEQ);
        const int4 q0 = __ldg(dp + tid);
        const int4 q1 = __ldg(dp + tid + THREADS);
        int acc = q0.x + q0.y + q0.z + q0.w + q1.x + q1.y + q1.z + q1.w;
        acc = __reduce_add_sync(0xFFFFFFFFu, acc);
        if (lane == 0) ws[warp] = acc;
        __syncthreads();
        int total = 0;
        #pragma unroll
        for (int i = 0; i < WARPS; i++) total += ws[i];

        const int base_frame = j * ZF_FRAMES;
        if (base_frame + ZF_FRAMES <= total) return;   // fully covered by copies

        const int base = base_frame * QUADS;           // float4 index within batch
        int end = (base_frame + ZF_FRAMES) * QUADS;
        const int tq = T * QUADS;
        if (end > tq) end = tq;
        const int lo = total * QUADS;                  // first padding float4

        float4* __restrict__ ob = reinterpret_cast<float4*>(out) + (size_t)b * tq;
        const float4 z = make_float4(0.f, 0.f, 0.f, 0.f);
        for (int e = base + tid; e < end; e += THREADS)
            if (e >= lo) __stcs(ob + e, z);
    }
}

extern "C" void kernel_launch(void* const* d_in, const int* in_sizes, int n_in,
                              void* d_out, int out_size)
{
    const float* x    = (const float*)d_in[0];   // [B, S, D] float32
    const int*   dims = (const int*)d_in[1];     // [B, S, 1] int32
    float*       out  = (float*)d_out;           // [B, T, D] float32

    const int T = out_size / (BATCH * DIM);
    const int zb_per_batch = (T + ZF_FRAMES - 1) / ZF_FRAMES;

    const int grid = NCOPY_BLOCKS + BATCH * zb_per_batch;
    expand_kernel<<<grid, THREADS>>>(x, dims, out, T, zb_per_batch);
}

// round 9
// speedup vs baseline: 1.0058x; 1.0058x over previous
#include <cuda_runtime.h>
#include <cstdint>

// Problem constants (fixed by the reference setup).
#define BATCH 16
#define SEQ   4096
#define DIM   256            // floats per frame
#define QUADS (DIM / 4)      // 64 float4 per frame

#define THREADS      512
#define WARPS        16
#define S_PER_BLOCK  16                          // one s per warp
#define CHUNKS_PER_BATCH (SEQ / S_PER_BLOCK)     // 256
#define NCOPY_BLOCKS (BATCH * CHUNKS_PER_BATCH)  // 4096
#define ZF_FRAMES    128                         // frames per zero-fill block

// Scratch: per-chunk partial sums of durations (16 s values per chunk).
__device__ int g_part[BATCH * CHUNKS_PER_BATCH];   // [b][c]

// ---------------------------------------------------------------------------
// Kernel 1: partials. One warp per 16-s chunk (4096 warps, 128 blocks).
// Highly parallel -> ~1.5us instead of the 16-block scan's 5.4us.
// ---------------------------------------------------------------------------
__global__ __launch_bounds__(1024) void partial_kernel(
    const int* __restrict__ dims)   // [B, S]
{
    const int w    = blockIdx.x * 32 + (threadIdx.x >> 5);  // 0..4095
    const int lane = threadIdx.x & 31;
    const int b    = w >> 8;
    const int c    = w & 255;

    int v = (lane < 16) ? __ldg(dims + (size_t)b * SEQ + (c << 4) + lane) : 0;
    v = __reduce_add_sync(0xFFFFFFFFu, v);
    if (lane == 0) g_part[w] = v;
}

// ---------------------------------------------------------------------------
// Kernel 2: expand. Two roles:
//  - copy blocks [0, 4096): 16 warps, one warp per (b,s). Block prefix =
//    sum of <=255 partials (one L2-hit LDG/thread + block reduce), intra-chunk
//    offsets from a 16-lane warp scan; each warp streams its prefetched 1KB
//    x row out d times (contiguous STG.128, streaming).
//  - zero-fill blocks: total_b = sum of 256 partials, then pad frames >=
//    total_b with zeros (stripes fully covered exit fast).
// ---------------------------------------------------------------------------
__global__ __launch_bounds__(THREADS) void expand_kernel(
    const float* __restrict__ x,     // [B, S, D]
    const int*   __restrict__ dims,  // [B, S]
    float* __restrict__ out,         // [B, T, D]
    int T, int zb_per_batch)
{
    const int tid  = threadIdx.x;
    const int warp = tid >> 5;
    const int lane = tid & 31;

    __shared__ int ws[WARPS];

    if (blockIdx.x < NCOPY_BLOCKS) {
        // ================= copy role =================
        const int cb     = blockIdx.x;
        const int b      = cb >> 8;             // 256 chunks per batch
        const int c      = cb & 255;
        const int s_base = c << 4;              // first s of this block
        const int s      = s_base + warp;       // this warp's source row

        // Issue all loads up front (latencies overlap).
        int p = (tid < c) ? __ldg(g_part + (b << 8) + tid) : 0;
        const int dval = (lane < 16)
            ? __ldg(dims + (size_t)b * SEQ + s_base + lane) : 0;

        const float4* __restrict__ src =
            reinterpret_cast<const float4*>(x) + ((size_t)b * SEQ + s) * QUADS;
        const float4 v0 = __ldg(src + lane);
        const float4 v1 = __ldg(src + lane + 32);

        // Block prefix = sum of partials [0, c).
        p = __reduce_add_sync(0xFFFFFFFFu, p);
        if (lane == 0) ws[warp] = p;
        __syncthreads();
        int prefix = 0;
        #pragma unroll
        for (int i = 0; i < WARPS; i++) prefix += ws[i];

        // Intra-chunk offsets: 16-lane inclusive scan of the chunk durations.
        int sc = dval;
        #pragma unroll
        for (int off = 1; off < 16; off <<= 1) {
            const int n = __shfl_up_sync(0xFFFFFFFFu, sc, off);
            if (lane >= off) sc += n;
        }
        const int d_own = __shfl_sync(0xFFFFFFFFu, dval, warp);
        const int incl  = __shfl_sync(0xFFFFFFFFu, sc,   warp);
        const int start = prefix + incl - d_own;     // exclusive prefix for s

        if (d_own == 0) return;

        float4* __restrict__ o = reinterpret_cast<float4*>(out)
                               + ((size_t)b * T + start) * QUADS;
        for (int k = 0; k < d_own; k++) {
            __stcs(o + lane,      v0);
            __stcs(o + lane + 32, v1);
            o += QUADS;
        }
        return;
    }

    // ================= zero-fill role =================
    {
        const int zb = blockIdx.x - NCOPY_BLOCKS;
        const int b  = zb / zb_per_batch;
        const int j  = zb - b * zb_per_batch;

        // total_b = sum of this batch's 256 partials.
        int p = (tid < CHUNKS_PER_BATCH) ? __ldg(g_part + (b << 8) + tid) : 0;
        p = __reduce_add_sync(0xFFFFFFFFu, p);
        if (lane == 0) ws[warp] = p;
        __syncthreads();
        int total = 0;
        #pragma unroll
        for (int i = 0; i < WARPS; i++) total += ws[i];

        const int base_frame = j * ZF_FRAMES;
        if (base_frame + ZF_FRAMES <= total) return;   // fully covered by copies

        const int base = base_frame * QUADS;           // float4 index within batch
        int end = (base_frame + ZF_FRAMES) * QUADS;
        const int tq = T * QUADS;
        if (end > tq) end = tq;
        const int lo = total * QUADS;                  // first padding float4

        float4* __restrict__ ob = reinterpret_cast<float4*>(out) + (size_t)b * tq;
        const float4 z = make_float4(0.f, 0.f, 0.f, 0.f);
        for (int e = base + tid; e < end; e += THREADS)
            if (e >= lo) __stcs(ob + e, z);
    }
}

extern "C" void kernel_launch(void* const* d_in, const int* in_sizes, int n_in,
                              void* d_out, int out_size)
{
    const float* x    = (const float*)d_in[0];   // [B, S, D] float32
    const int*   dims = (const int*)d_in[1];     // [B, S, 1] int32
    float*       out  = (float*)d_out;           // [B, T, D] float32

    const int T = out_size / (BATCH * DIM);
    const int zb_per_batch = (T + ZF_FRAMES - 1) / ZF_FRAMES;

    partial_kernel<<<NCOPY_BLOCKS / 32, 1024>>>(dims);

    const int grid = NCOPY_BLOCKS + BATCH * zb_per_batch;
    expand_kernel<<<grid, THREADS>>>(x, dims, out, T, zb_per_batch);
}

// round 10
// speedup vs baseline: 1.0419x; 1.0359x over previous
#include <cuda_runtime.h>
#include <cstdint>

// Problem constants (fixed by the reference setup).
#define BATCH 16
#define SEQ   4096
#define DIM   256            // floats per frame
#define QUADS (DIM / 4)      // 64 float4 per frame

#define CHUNK        16                          // s values per chunk
#define CHUNKS_PER_BATCH (SEQ / CHUNK)           // 256
#define NCHUNKS      (BATCH * CHUNKS_PER_BATCH)  // 4096
#define NCOPY_BLOCKS ((BATCH * SEQ) / 8)         // 8192 (8 warps/block, 1 warp/s)
#define ZF_FRAMES    64                          // frames per zero-fill block

// Scratch: per-chunk partial sums of durations.
__device__ int g_part[NCHUNKS];   // [b][c]

// ---------------------------------------------------------------------------
// Kernel 1: partials. One warp per 16-s chunk (4096 warps, 128 blocks).
// ---------------------------------------------------------------------------
__global__ __launch_bounds__(1024) void partial_kernel(
    const int* __restrict__ dims)   // [B, S]
{
    const int w    = blockIdx.x * 32 + (threadIdx.x >> 5);  // 0..4095
    const int lane = threadIdx.x & 31;

    int v = (lane < CHUNK) ? __ldg(dims + (size_t)w * CHUNK + lane) : 0;
    v = __reduce_add_sync(0xFFFFFFFFu, v);
    if (lane == 0) g_part[w] = v;
}

// ---------------------------------------------------------------------------
// Kernel 2: expand. NO shared memory, NO __syncthreads — every warp fully
// independent (the 512-thread block-coupled variants all cost +4-5us).
//  - copy warps: one warp per (b,s). Warp prefetches its 1KB x row, privately
//    computes start = sum(partials[b][0:c)) + intra-chunk scan (all L2-hit,
//    hidden under the prefetch), then streams d contiguous copies out.
//  - zero-fill warps: compute total_b from the 256 partials warp-locally,
//    then pad frames >= total_b with zeros.
// ---------------------------------------------------------------------------
__global__ __launch_bounds__(256) void expand_kernel(
    const float* __restrict__ x,     // [B, S, D]
    const int*   __restrict__ dims,  // [B, S]
    float* __restrict__ out,         // [B, T, D]
    int T, int zb_per_batch)
{
    const int warp = threadIdx.x >> 5;
    const int lane = threadIdx.x & 31;

    if (blockIdx.x < NCOPY_BLOCKS) {
        // ================= copy role =================
        const int gw = blockIdx.x * 8 + warp;        // 0 .. B*SEQ-1 (one warp per s)
        const int b  = gw >> 12;                     // SEQ = 4096
        const int sl = gw & (SEQ - 1);               // s within batch
        const int c  = sl >> 4;                      // chunk index, 0..255
        const int r  = sl & (CHUNK - 1);             // rank within chunk

        // --- issue prefix loads first; then prefetch x (latencies overlap) ---
        const int* __restrict__ pb = g_part + (b << 8);
        int p = 0;
        #pragma unroll
        for (int i = 0; i < 8; i++) {
            const int j = lane + (i << 5);
            if (j < c) p += __ldg(pb + j);
        }
        const int dval = (lane < CHUNK)
            ? __ldg(dims + ((size_t)b << 12) + (c << 4) + lane) : 0;

        const float4* __restrict__ src =
            reinterpret_cast<const float4*>(x) + (size_t)gw * QUADS;
        const float4 v0 = __ldg(src + lane);
        const float4 v1 = __ldg(src + lane + 32);

        // --- chunk start = reduce of predecessor partials ---
        p = __reduce_add_sync(0xFFFFFFFFu, p);

        // --- intra-chunk offset: 16-lane inclusive scan of chunk durations ---
        int sc = dval;
        #pragma unroll
        for (int off = 1; off < CHUNK; off <<= 1) {
            const int n = __shfl_up_sync(0xFFFFFFFFu, sc, off);
            if (lane >= off) sc += n;
        }
        const int d_own = __shfl_sync(0xFFFFFFFFu, dval, r);
        const int incl  = __shfl_sync(0xFFFFFFFFu, sc,   r);
        const int start = p + incl - d_own;          // exclusive prefix for s

        if (d_own == 0) return;

        float4* __restrict__ o = reinterpret_cast<float4*>(out)
                               + ((size_t)b * T + start) * QUADS;
        for (int k = 0; k < d_own; k++) {
            __stcs(o + lane,      v0);
            __stcs(o + lane + 32, v1);
            o += QUADS;
        }
        return;
    }

    // ================= zero-fill role (warp-local total, no sync) =================
    {
        const int zb = blockIdx.x - NCOPY_BLOCKS;
        const int b  = zb / zb_per_batch;
        const int j  = zb - b * zb_per_batch;

        // total_b = sum of this batch's 256 partials (8 per lane).
        const int* __restrict__ pb = g_part + (b << 8);
        int p = 0;
        #pragma unroll
        for (int i = 0; i < 8; i++) p += __ldg(pb + lane + (i << 5));
        const int total = __reduce_add_sync(0xFFFFFFFFu, p);

        const int base_frame = j * ZF_FRAMES;
        if (base_frame + ZF_FRAMES <= total) return;   // fully covered by copies

        const int base = base_frame * QUADS;           // float4 index within batch
        int end = (base_frame + ZF_FRAMES) * QUADS;
        const int tq = T * QUADS;
        if (end > tq) end = tq;
        const int lo = total * QUADS;                  // first padding float4

        float4* __restrict__ ob = reinterpret_cast<float4*>(out) + (size_t)b * tq;
        const float4 z = make_float4(0.f, 0.f, 0.f, 0.f);
        for (int e = base + threadIdx.x; e < end; e += 256)
            if (e >= lo) __stcs(ob + e, z);
    }
}

extern "C" void kernel_launch(void* const* d_in, const int* in_sizes, int n_in,
                              void* d_out, int out_size)
{
    const float* x    = (const float*)d_in[0];   // [B, S, D] float32
    const int*   dims = (const int*)d_in[1];     // [B, S, 1] int32
    float*       out  = (float*)d_out;           // [B, T, D] float32

    const int T = out_size / (BATCH * DIM);
    const int zb_per_batch = (T + ZF_FRAMES - 1) / ZF_FRAMES;

    partial_kernel<<<NCHUNKS / 32, 1024>>>(dims);

    const int grid = NCOPY_BLOCKS + BATCH * zb_per_batch;
    expand_kernel<<<grid, 256>>>(x, dims, out, T, zb_per_batch);
}

// round 11
// speedup vs baseline: 1.0761x; 1.0328x over previous
#include <cuda_runtime.h>
#include <cstdint>

// Problem constants (fixed by the reference setup).
#define BATCH 16
#define SEQ   4096
#define DIM   256            // floats per frame
#define QUADS (DIM / 4)      // 64 float4 per frame

#define CHUNK        16                          // s values per level-1 chunk
#define CHUNKS_PER_BATCH (SEQ / CHUNK)           // 256
#define NCHUNKS      (BATCH * CHUNKS_PER_BATCH)  // 4096
#define SUPER        256                         // s values per level-2 super-chunk
#define SUPERS_PER_BATCH (SEQ / SUPER)           // 16
#define NSUPER       (BATCH * SUPERS_PER_BATCH)  // 256
#define NCOPY_BLOCKS ((BATCH * SEQ) / 8)         // 8192 (8 warps/block, 1 warp/s)
#define ZF_FRAMES    64                          // frames per zero-fill block

// Scratch: two-level partial sums of durations.
__device__ int g_part [NCHUNKS];   // [b][c]  sum of 16 durations
__device__ int g_super[NSUPER];    // [b][cs] sum of 256 durations

// ---------------------------------------------------------------------------
// Kernel 1: partials, both levels, each computed directly from dims
// (no inter-level dependency). One warp per chunk / super-chunk.
// ---------------------------------------------------------------------------
__global__ __launch_bounds__(1024) void partial_kernel(
    const int* __restrict__ dims)   // [B, S]
{
    const int w    = blockIdx.x * 32 + (threadIdx.x >> 5);
    const int lane = threadIdx.x & 31;

    if (w < NCHUNKS) {
        // level 1: sum of 16 durations
        int v = (lane < CHUNK) ? __ldg(dims + (size_t)w * CHUNK + lane) : 0;
        v = __reduce_add_sync(0xFFFFFFFFu, v);
        if (lane == 0) g_part[w] = v;
    } else {
        // level 2: sum of 256 durations (64 int4, 2 per lane)
        const int s = w - NCHUNKS;                 // 0..255 == b*16 + cs
        const int4* dp = reinterpret_cast<const int4*>(dims) + (size_t)s * 64;
        const int4 a = __ldg(dp + lane);
        const int4 b = __ldg(dp + lane + 32);
        int v = a.x + a.y + a.z + a.w + b.x + b.y + b.z + b.w;
        v = __reduce_add_sync(0xFFFFFFFFu, v);
        if (lane == 0) g_super[s] = v;
    }
}

// ---------------------------------------------------------------------------
// Kernel 2: expand. No shared memory, no __syncthreads — warps independent.
//  - copy warps: one warp per (b,s). Chunk start = ONE 32-lane reduce:
//      lanes 0..15  carry predecessor super-chunk sums   (< cs)
//      lanes 16..31 carry predecessor level-1 sums within the current super
//    then a 16-lane scan of the chunk's own durations gives the offset.
//    All prefix loads are L2-hit and overlap the warp's x-row prefetch.
//  - zero-fill warps: total_b = reduce of the 16 super sums.
// ---------------------------------------------------------------------------
__global__ __launch_bounds__(256) void expand_kernel(
    const float* __restrict__ x,     // [B, S, D]
    const int*   __restrict__ dims,  // [B, S]
    float* __restrict__ out,         // [B, T, D]
    int T, int zb_per_batch)
{
    const int warp = threadIdx.x >> 5;
    const int lane = threadIdx.x & 31;

    if (blockIdx.x < NCOPY_BLOCKS) {
        // ================= copy role =================
        const int gw = blockIdx.x * 8 + warp;        // 0 .. B*SEQ-1 (one warp per s)
        const int b  = gw >> 12;                     // SEQ = 4096
        const int sl = gw & (SEQ - 1);               // s within batch
        const int c  = sl >> 4;                      // chunk index, 0..255
        const int cs = c >> 4;                       // super index, 0..15
        const int cm = c & 15;                       // chunk within super
        const int r  = sl & (CHUNK - 1);             // rank within chunk

        // --- prefix loads: 1 masked LDG per lane, split across half-warps ---
        int p = 0;
        if (lane < 16) {
            if (lane < cs) p = __ldg(g_super + (b << 4) + lane);
        } else {
            const int j = lane - 16;
            if (j < cm)  p = __ldg(g_part + (b << 8) + (cs << 4) + j);
        }
        const int dval = (lane < CHUNK)
            ? __ldg(dims + ((size_t)b << 12) + (c << 4) + lane) : 0;

        // --- prefetch this warp's 1KB source row (2 independent LDG.128) ---
        const float4* __restrict__ src =
            reinterpret_cast<const float4*>(x) + (size_t)gw * QUADS;
        const float4 v0 = __ldg(src + lane);
        const float4 v1 = __ldg(src + lane + 32);

        // --- chunk start ---
        p = __reduce_add_sync(0xFFFFFFFFu, p);

        // --- intra-chunk offset: 16-lane inclusive scan of chunk durations ---
        int sc = dval;
        #pragma unroll
        for (int off = 1; off < CHUNK; off <<= 1) {
            const int n = __shfl_up_sync(0xFFFFFFFFu, sc, off);
            if (lane >= off) sc += n;
        }
        const int d_own = __shfl_sync(0xFFFFFFFFu, dval, r);
        const int incl  = __shfl_sync(0xFFFFFFFFu, sc,   r);
        const int start = p + incl - d_own;          // exclusive prefix for s

        if (d_own == 0) return;

        float4* __restrict__ o = reinterpret_cast<float4*>(out)
                               + ((size_t)b * T + start) * QUADS;
        for (int k = 0; k < d_own; k++) {
            __stcs(o + lane,      v0);
            __stcs(o + lane + 32, v1);
            o += QUADS;
        }
        return;
    }

    // ================= zero-fill role (warp-local total, no sync) =================
    {
        const int zb = blockIdx.x - NCOPY_BLOCKS;
        const int b  = zb / zb_per_batch;
        const int j  = zb - b * zb_per_batch;

        // total_b = sum of this batch's 16 super sums.
        int p = (lane < SUPERS_PER_BATCH) ? __ldg(g_super + (b << 4) + lane) : 0;
        const int total = __reduce_add_sync(0xFFFFFFFFu, p);

        const int base_frame = j * ZF_FRAMES;
        if (base_frame + ZF_FRAMES <= total) return;   // fully covered by copies

        const int base = base_frame * QUADS;           // float4 index within batch
        int end = (base_frame + ZF_FRAMES) * QUADS;
        const int tq = T * QUADS;
        if (end > tq) end = tq;
        const int lo = total * QUADS;                  // first padding float4

        float4* __restrict__ ob = reinterpret_cast<float4*>(out) + (size_t)b * tq;
        const float4 z = make_float4(0.f, 0.f, 0.f, 0.f);
        for (int e = base + threadIdx.x; e < end; e += 256)
            if (e >= lo) __stcs(ob + e, z);
    }
}

extern "C" void kernel_launch(void* const* d_in, const int* in_sizes, int n_in,
                              void* d_out, int out_size)
{
    const float* x    = (const float*)d_in[0];   // [B, S, D] float32
    const int*   dims = (const int*)d_in[1];     // [B, S, 1] int32
    float*       out  = (float*)d_out;           // [B, T, D] float32

    const int T = out_size / (BATCH * DIM);
    const int zb_per_batch = (T + ZF_FRAMES - 1) / ZF_FRAMES;

    partial_kernel<<<(NCHUNKS + NSUPER) / 32, 1024>>>(dims);

    const int grid = NCOPY_BLOCKS + BATCH * zb_per_batch;
    expand_kernel<<<grid, 256>>>(x, dims, out, T, zb_per_batch);
}